// round 17
// baseline (speedup 1.0000x reference)
#include <cuda_runtime.h>
#include <cuda_bf16.h>
#include <math.h>
#include <stdint.h>

#define NN   50000
#define FH   128
#define NTOT (4 * NN)
#define CSRMAX 2200000
#define SCAN_B ((NTOT + 1023) / 1024)
#define NWELEM (18 * 16384)
#define NXELEM (NN * FH)

// ===================== scratch (static device globals) =====================
__device__ int           g_degi[NTOT];          // zero-init; re-zeroed by gather each launch
__device__ int           g_offs[NTOT + 1];      // block-local exclusive; [NTOT] = grand total
__device__ int           g_cur[NTOT];           // zero-init; re-zeroed by gather each launch
__device__ int           g_part[SCAN_B];        // per-block exclusive base
__device__ int           g_csr[CSRMAX];
__device__ __nv_bfloat16 g_pq[(size_t)2 * NN * FH];   // P = emb@W1a, Q = emb@W1b (bf16)
__device__ __nv_bfloat16 g_x[(size_t)NN * FH];
__device__ __nv_bfloat16 g_agg[(size_t)4 * NN * FH];
__device__ __nv_bfloat16 g_h1[(size_t)4 * NN * FH];
__device__ __nv_bfloat16 g_hs[(size_t)4 * NN * FH];
__device__ __nv_bfloat16 g_emb[(size_t)NN * FH];
__device__ __nv_bfloat16 g_whi[NWELEM];   // [mat][n][k]

__device__ __forceinline__ uint32_t pack_bf16(__nv_bfloat16 a, __nv_bfloat16 b) {
    return (uint32_t)__bfloat16_as_ushort(a) | ((uint32_t)__bfloat16_as_ushort(b) << 16);
}
__device__ __forceinline__ uint32_t pack2f(float a, float b) {
    return pack_bf16(__float2bfloat16(a), __float2bfloat16(b));
}
__device__ __forceinline__ uint32_t smem_u32(const void* p) {
    uint32_t a;
    asm("{ .reg .u64 t; cvta.to.shared.u64 t, %1; cvt.u32.u64 %0, t; }" : "=r"(a) : "l"(p));
    return a;
}
__device__ __forceinline__ uint32_t swz(uint32_t off) { return off ^ ((off >> 3) & 0x70); }

__device__ __forceinline__ void ldm_x4(uint32_t addr, uint32_t* r) {
    asm volatile("ldmatrix.sync.aligned.m8n8.x4.shared.b16 {%0,%1,%2,%3}, [%4];"
                 : "=r"(r[0]), "=r"(r[1]), "=r"(r[2]), "=r"(r[3]) : "r"(addr));
}
__device__ __forceinline__ void mma16816(float* c, const uint32_t* a, const uint32_t* b) {
    asm volatile("mma.sync.aligned.m16n8k16.row.col.f32.bf16.bf16.f32 "
        "{%0,%1,%2,%3}, {%4,%5,%6,%7}, {%8,%9}, {%0,%1,%2,%3};"
        : "+f"(c[0]), "+f"(c[1]), "+f"(c[2]), "+f"(c[3])
        : "r"(a[0]), "r"(a[1]), "r"(a[2]), "r"(a[3]), "r"(b[0]), "r"(b[1]));
}
__device__ __forceinline__ void cpasync16z(uint32_t dst, const void* src, int src_bytes) {
    asm volatile("cp.async.ca.shared.global [%0], [%1], 16, %2;"
                 :: "r"(dst), "l"(__cvta_generic_to_global(src)), "r"(src_bytes) : "memory");
}
#define CP_COMMIT() asm volatile("cp.async.commit_group;" ::: "memory")
#define CP_WAIT0()  asm volatile("cp.async.wait_group 0;" ::: "memory")
#define CP_WAIT1()  asm volatile("cp.async.wait_group 1;" ::: "memory")

struct EdgeArgs {
    const int* src[4]; const int* dst[4];
    int off[5];
};

// ===================== prologue: W convert + x convert + degree count, one launch =====================
__global__ void prologue_kernel(const float* __restrict__ Ws1, const float* __restrict__ Wn1,
                                const float* __restrict__ Ws2, const float* __restrict__ Wn2,
                                const float* __restrict__ L1, const float* __restrict__ x,
                                EdgeArgs a) {
    int g = blockIdx.x * blockDim.x + threadIdx.x;
    if (g < NWELEM) {
        int m = g >> 14, r = g & 16383, n = r >> 7, k = r & 127;
        const float* s;
        if (m < 4)       s = Ws1 + (size_t)m * 16384;
        else if (m < 8)  s = Wn1 + (size_t)(m - 4) * 16384;
        else if (m < 12) s = Ws2 + (size_t)(m - 8) * 16384;
        else if (m < 16) s = Wn2 + (size_t)(m - 12) * 16384;
        else             s = L1  + (size_t)(m - 16) * 16384;
        g_whi[(size_t)m * 16384 + n * 128 + k] = __float2bfloat16(s[k * 128 + n]);
    } else if (g < NWELEM + NXELEM) {
        int i = g - NWELEM;
        g_x[i] = __float2bfloat16(x[i]);
    } else {
        int w = g - NWELEM - NXELEM;
        if (w < a.off[4]) {
            int y = (w >= a.off[1]) + (w >= a.off[2]) + (w >= a.off[3]);
            atomicAdd(&g_degi[y * NN + __ldg(a.dst[y] + (w - a.off[y]))], 1);
        }
    }
}

// ---------- scan (2 launches; bases folded into consumers) ----------
__global__ void scan1_kernel() {
    __shared__ int sh[1024];
    int t = threadIdx.x;
    int i = blockIdx.x * 1024 + t;
    int v = (i < NTOT) ? g_degi[i] : 0;
    sh[t] = v;
    __syncthreads();
#pragma unroll
    for (int o = 1; o < 1024; o <<= 1) {
        int add = (t >= o) ? sh[t - o] : 0;
        __syncthreads();
        sh[t] += add;
        __syncthreads();
    }
    if (i < NTOT) g_offs[i] = sh[t] - v;      // block-local exclusive
    if (t == 1023) g_part[blockIdx.x] = sh[1023];
}

__global__ void scan2_kernel() {
    __shared__ int sh[256];
    int t = threadIdx.x;
    int v = (t < SCAN_B) ? g_part[t] : 0;
    sh[t] = v;
    __syncthreads();
#pragma unroll
    for (int o = 1; o < 256; o <<= 1) {
        int add = (t >= o) ? sh[t - o] : 0;
        __syncthreads();
        sh[t] += add;
        __syncthreads();
    }
    if (t < SCAN_B) g_part[t] = sh[t] - v;    // exclusive base per block
    if (t == 255) g_offs[NTOT] = sh[255];     // grand total (absolute)
}

__device__ __forceinline__ int abs_off(int i) {   // absolute offset for i in [0, NTOT]
    return (i == NTOT) ? g_offs[NTOT] : (g_offs[i] + g_part[i >> 10]);
}

__global__ void fill_kernel(EdgeArgs a) {
    int w = blockIdx.x * blockDim.x + threadIdx.x;
    if (w >= a.off[4]) return;
    int y = (w >= a.off[1]) + (w >= a.off[2]) + (w >= a.off[3]);
    int e = w - a.off[y];
    int s = __ldg(a.src[y] + e), d = __ldg(a.dst[y] + e);
    int node = y * NN + d;
    int pos = abs_off(node) + atomicAdd(&g_cur[node], 1);
    g_csr[pos] = s;
}

// ---------- CSR gather aggregation: one warp per (metapath,node), 4-edge ILP ----------
// Also re-zeroes g_degi/g_cur for the next graph replay.
__global__ void gather_kernel(const __nv_bfloat16* __restrict__ src, size_t ystride) {
    int g = (blockIdx.x * blockDim.x + threadIdx.x) >> 5;
    if (g >= NTOT) return;
    int lane = threadIdx.x & 31;
    int y = g / NN;
    const __nv_bfloat16* base = src + (size_t)y * ystride;
    int o0 = abs_off(g), o1 = abs_off(g + 1);
    if (lane == 0) { g_degi[g] = 0; g_cur[g] = 0; }
    float4 acc0 = make_float4(0.f, 0.f, 0.f, 0.f);
    float4 acc1 = make_float4(0.f, 0.f, 0.f, 0.f);
    int j = o0;
    for (; j + 3 < o1; j += 4) {
        int s0 = __ldg(g_csr + j),     s1 = __ldg(g_csr + j + 1);
        int s2 = __ldg(g_csr + j + 2), s3 = __ldg(g_csr + j + 3);
        uint2 h0 = __ldg((const uint2*)(base + (size_t)s0 * FH) + lane);
        uint2 h1 = __ldg((const uint2*)(base + (size_t)s1 * FH) + lane);
        uint2 h2 = __ldg((const uint2*)(base + (size_t)s2 * FH) + lane);
        uint2 h3 = __ldg((const uint2*)(base + (size_t)s3 * FH) + lane);
        float2 a0 = __bfloat1622float2(*(__nv_bfloat162*)&h0.x);
        float2 b0 = __bfloat1622float2(*(__nv_bfloat162*)&h0.y);
        float2 a1 = __bfloat1622float2(*(__nv_bfloat162*)&h1.x);
        float2 b1 = __bfloat1622float2(*(__nv_bfloat162*)&h1.y);
        float2 a2 = __bfloat1622float2(*(__nv_bfloat162*)&h2.x);
        float2 b2 = __bfloat1622float2(*(__nv_bfloat162*)&h2.y);
        float2 a3 = __bfloat1622float2(*(__nv_bfloat162*)&h3.x);
        float2 b3 = __bfloat1622float2(*(__nv_bfloat162*)&h3.y);
        acc0.x += a0.x + a2.x; acc0.y += a0.y + a2.y; acc0.z += b0.x + b2.x; acc0.w += b0.y + b2.y;
        acc1.x += a1.x + a3.x; acc1.y += a1.y + a3.y; acc1.z += b1.x + b3.x; acc1.w += b1.y + b3.y;
    }
    for (; j < o1; ++j) {
        int s0 = __ldg(g_csr + j);
        uint2 h0 = __ldg((const uint2*)(base + (size_t)s0 * FH) + lane);
        float2 a0 = __bfloat1622float2(*(__nv_bfloat162*)&h0.x);
        float2 b0 = __bfloat1622float2(*(__nv_bfloat162*)&h0.y);
        acc0.x += a0.x; acc0.y += a0.y; acc0.z += b0.x; acc0.w += b0.y;
    }
    float sc = 1.0f / fmaxf((float)(o1 - o0), 1.0f);
    float ax = (acc0.x + acc1.x) * sc, ay = (acc0.y + acc1.y) * sc;
    float az = (acc0.z + acc1.z) * sc, aw = (acc0.w + acc1.w) * sc;
    *(uint2*)(g_agg + (size_t)g * FH + lane * 4) = make_uint2(pack2f(ax, ay), pack2f(az, aw));
}

// attention softmax over 4 metapaths -> emb bf16; one warp per node
__global__ void attention_kernel(const float* __restrict__ attW, const float* __restrict__ attB) {
    int n = (blockIdx.x * blockDim.x + threadIdx.x) >> 5;
    if (n >= NN) return;
    int lane = threadIdx.x & 31;
    float4 hv[4]; float logit[4];
#pragma unroll
    for (int k = 0; k < 4; ++k) {
        uint2 h = __ldg((const uint2*)(g_hs + ((size_t)k * NN + n) * FH) + lane);
        float2 h01 = __bfloat1622float2(*(__nv_bfloat162*)&h.x);
        float2 h23 = __bfloat1622float2(*(__nv_bfloat162*)&h.y);
        float4 h4 = make_float4(h01.x, h01.y, h23.x, h23.y);
        float4 w4 = *(const float4*)(attW + k * FH + lane * 4);
        hv[k] = h4;
        float p = h4.x * w4.x + h4.y * w4.y + h4.z * w4.z + h4.w * w4.w;
#pragma unroll
        for (int o2 = 16; o2; o2 >>= 1) p += __shfl_xor_sync(0xffffffffu, p, o2);
        logit[k] = p + attB[k];
    }
    float m = fmaxf(fmaxf(logit[0], logit[1]), fmaxf(logit[2], logit[3]));
    float e[4], s = 0.0f;
#pragma unroll
    for (int k = 0; k < 4; ++k) { e[k] = expf(logit[k] - m); s += e[k]; }
    float is = 1.0f / s;
    float4 o = make_float4(0.f, 0.f, 0.f, 0.f);
#pragma unroll
    for (int k = 0; k < 4; ++k) {
        float w = e[k] * is;
        o.x += w * hv[k].x; o.y += w * hv[k].y; o.z += w * hv[k].z; o.w += w * hv[k].w;
    }
    *(uint2*)(g_emb + (size_t)n * FH + lane * 4) = make_uint2(pack2f(o.x, o.y), pack2f(o.z, o.w));
}

// edge scorer: score = sigmoid(sum relu(P[s]+Q[d]+b) * w2 + b2); one warp per edge; bf16 P/Q.
__global__ void edge_score_kernel(const int* __restrict__ src, const int* __restrict__ dst,
                                  const float* __restrict__ l1b, const float* __restrict__ l2w,
                                  const float* __restrict__ l2b,
                                  float* __restrict__ out, int ne) {
    int e = (blockIdx.x * blockDim.x + threadIdx.x) >> 5;
    if (e >= ne) return;
    int lane = threadIdx.x & 31;
    int s = __ldg(src + e), d = __ldg(dst + e);
    uint2 pu = __ldg((const uint2*)(g_pq + (size_t)s * FH) + lane);
    uint2 qu = __ldg((const uint2*)(g_pq + (size_t)NN * FH + (size_t)d * FH) + lane);
    float2 p01 = __bfloat1622float2(*(__nv_bfloat162*)&pu.x);
    float2 p23 = __bfloat1622float2(*(__nv_bfloat162*)&pu.y);
    float2 q01 = __bfloat1622float2(*(__nv_bfloat162*)&qu.x);
    float2 q23 = __bfloat1622float2(*(__nv_bfloat162*)&qu.y);
    float4 b = *(const float4*)(l1b + lane * 4);
    float4 w = *(const float4*)(l2w + lane * 4);
    float acc = fmaxf(p01.x + q01.x + b.x, 0.f) * w.x + fmaxf(p01.y + q01.y + b.y, 0.f) * w.y
              + fmaxf(p23.x + q23.x + b.z, 0.f) * w.z + fmaxf(p23.y + q23.y + b.w, 0.f) * w.w;
#pragma unroll
    for (int o = 16; o; o >>= 1) acc += __shfl_xor_sync(0xffffffffu, acc, o);
    if (lane == 0) out[e] = 1.0f / (1.0f + expf(-(acc + __ldg(l2b))));
}

// ===================== mma.sync GEMM: single bf16 pass, cp.async double-buffer =====================
// MODE 0: 2 halves, bias+relu -> bf16.  MODE 1: 2 halves, +bias -> bf16.
// MODE 3: single half (K=128), no bias -> bf16.
#define SB_BIAS 0
#define SB_TILES 1024
#define TILE_SZ 16384
#define SMEM_TOTAL (SB_TILES + 4 * TILE_SZ)   // 2 stages x (A,W)

__device__ __forceinline__ void stage_tile(uint32_t stile, const __nv_bfloat16* gbase,
                                           int row0, int nrows, int kofs, int tid) {
#pragma unroll
    for (int i = tid; i < 1024; i += 256) {
        int r = i >> 3, j = i & 7;
        int grow = row0 + r;
        bool valid = grow < nrows;
        const __nv_bfloat16* src = gbase + (size_t)(valid ? grow : 0) * FH + kofs + j * 8;
        uint32_t off = (uint32_t)(r * 128 + j * 16);
        cpasync16z(stile + swz(off), src, valid ? 16 : 0);
    }
}

__device__ __forceinline__ void load_a_frag(uint32_t tb, int wm, int ks, int lane, uint32_t* ra) {
    int q = lane >> 3, r = lane & 7;
    int rofs = ((q & 1) ? 8 : 0) + r;
    int kl = ks * 16 + ((q & 2) ? 8 : 0);
#pragma unroll
    for (int mf = 0; mf < 4; ++mf) {
        uint32_t off = (uint32_t)((wm * 64 + mf * 16 + rofs) * 128 + kl * 2);
        ldm_x4(tb + swz(off), ra + mf * 4);
    }
}
__device__ __forceinline__ void load_w_frag(uint32_t tb, int wn, int ks, int lane, uint32_t* rw) {
    int q = lane >> 3, r = lane & 7;
    int rofs = ((q & 2) ? 8 : 0) + r;
    int kl = ks * 16 + ((q & 1) ? 8 : 0);
#pragma unroll
    for (int pf = 0; pf < 2; ++pf) {
        uint32_t off = (uint32_t)((wn * 32 + pf * 16 + rofs) * 128 + kl * 2);
        ldm_x4(tb + swz(off), rw + pf * 4);
    }
}

template <int MODE>
__global__ void __launch_bounds__(256) mp_gemm_kernel(
    const __nv_bfloat16* __restrict__ a0, size_t a0stride,
    const __nv_bfloat16* __restrict__ a1, size_t a1stride,
    int w0mat, int w1mat, int wmatstride,
    const float* __restrict__ bias, int bstride,
    __nv_bfloat16* __restrict__ outb, size_t outbstride,
    int nrows)
{
    extern __shared__ char smem[];
    const uint32_t sb = smem_u32(smem);
    const int tid = threadIdx.x, lane = tid & 31, wid = tid >> 5;
    const int wm = wid & 1, wn = wid >> 1;
    const int y = blockIdx.y;
    const int row0 = blockIdx.x * 128;

    float* sbias = (float*)(smem + SB_BIAS);
    if (tid < 128) sbias[tid] = (MODE == 3) ? 0.f : bias[bstride * y + tid];

    const __nv_bfloat16* ab[2] = { a0 + (size_t)y * a0stride, a1 + (size_t)y * a1stride };
    const int wm0 = w0mat + y * wmatstride, wm1 = w1mat + y * wmatstride;

    float acc[4][4][4];
#pragma unroll
    for (int i = 0; i < 4; ++i)
#pragma unroll
        for (int j = 0; j < 4; ++j)
#pragma unroll
            for (int q = 0; q < 4; ++q) acc[i][j][q] = 0.0f;

    const int CHUNKS = (MODE == 3) ? 2 : 4;
    // prologue: stage chunk 0 into buffer 0
    stage_tile(sb + SB_TILES, ab[0], row0, nrows, 0, tid);
    stage_tile(sb + SB_TILES + TILE_SZ, g_whi + (size_t)wm0 * 16384, 0, 128, 0, tid);
    CP_COMMIT();

#pragma unroll 1
    for (int c = 0; c < CHUNKS; ++c) {
        if (c + 1 < CHUNKS) {
            const int nh = (MODE == 3) ? 0 : ((c + 1) >> 1), nkc = ((c + 1) & 1) * 64;
            const uint32_t nbuf = sb + SB_TILES + ((c + 1) & 1) * 2 * TILE_SZ;
            stage_tile(nbuf, ab[nh], row0, nrows, nkc, tid);
            stage_tile(nbuf + TILE_SZ, g_whi + (size_t)(nh ? wm1 : wm0) * 16384, 0, 128, nkc, tid);
            CP_COMMIT();
            CP_WAIT1();
        } else {
            CP_WAIT0();
        }
        __syncthreads();
        const uint32_t buf = sb + SB_TILES + (c & 1) * 2 * TILE_SZ;
        const uint32_t tA = buf, tW = buf + TILE_SZ;
#pragma unroll
        for (int ks = 0; ks < 4; ++ks) {
            uint32_t ra[16], rw[8];
            load_a_frag(tA, wm, ks, lane, ra);
            load_w_frag(tW, wn, ks, lane, rw);
#pragma unroll
            for (int mf = 0; mf < 4; ++mf)
#pragma unroll
                for (int nf = 0; nf < 4; ++nf)
                    mma16816(acc[mf][nf], ra + mf * 4, rw + nf * 2);
        }
        if (c + 1 < CHUNKS) __syncthreads();   // done reading buf before it is re-staged
    }

    // ---------------- epilogue ----------------
    const int rbase = row0 + wm * 64 + (lane >> 2);
    const int cbase = wn * 32 + 2 * (lane & 3);

#pragma unroll
    for (int mf = 0; mf < 4; ++mf) {
        int r0 = rbase + mf * 16, r1 = r0 + 8;
        bool v0 = r0 < nrows, v1 = r1 < nrows;
#pragma unroll
        for (int nf = 0; nf < 4; ++nf) {
            int gc = cbase + nf * 8;
            float b0v = sbias[gc], b1v = sbias[gc + 1];
            float e0 = acc[mf][nf][0] + b0v, e1 = acc[mf][nf][1] + b1v;
            float e2 = acc[mf][nf][2] + b0v, e3 = acc[mf][nf][3] + b1v;
            if (MODE == 0) {
                e0 = fmaxf(e0, 0.f); e1 = fmaxf(e1, 0.f);
                e2 = fmaxf(e2, 0.f); e3 = fmaxf(e3, 0.f);
            }
            if (v0) *(uint32_t*)(outb + (size_t)y * outbstride + (size_t)r0 * FH + gc) = pack2f(e0, e1);
            if (v1) *(uint32_t*)(outb + (size_t)y * outbstride + (size_t)r1 * FH + gc) = pack2f(e2, e3);
        }
    }
}

// ===================== host =====================
extern "C" void kernel_launch(void* const* d_in, const int* in_sizes, int n_in,
                              void* d_out, int out_size) {
    const float* x    = (const float*)d_in[0];
    const float* Ws1  = (const float*)d_in[1];
    const float* b1   = (const float*)d_in[2];
    const float* Wn1  = (const float*)d_in[3];
    const float* Ws2  = (const float*)d_in[4];
    const float* b2   = (const float*)d_in[5];
    const float* Wn2  = (const float*)d_in[6];
    const float* attW = (const float*)d_in[7];
    const float* attB = (const float*)d_in[8];
    const float* l1W  = (const float*)d_in[9];
    const float* l1b  = (const float*)d_in[10];
    const float* l2W  = (const float*)d_in[11];
    const float* l2b  = (const float*)d_in[12];
    const int* srcs[4] = {(const int*)d_in[13], (const int*)d_in[15],
                          (const int*)d_in[17], (const int*)d_in[19]};
    const int* dsts[4] = {(const int*)d_in[14], (const int*)d_in[16],
                          (const int*)d_in[18], (const int*)d_in[20]};
    const int* ssim = (const int*)d_in[21];
    const int* dsim = (const int*)d_in[22];
    const int  esim = in_sizes[21];

    void *pqP, *xP, *aggP, *h1P, *hsP, *embP;
    cudaGetSymbolAddress(&pqP, g_pq);
    cudaGetSymbolAddress(&xP, g_x);
    cudaGetSymbolAddress(&aggP, g_agg);
    cudaGetSymbolAddress(&h1P, g_h1);
    cudaGetSymbolAddress(&hsP, g_hs);
    cudaGetSymbolAddress(&embP, g_emb);

    cudaFuncSetAttribute(mp_gemm_kernel<0>, cudaFuncAttributeMaxDynamicSharedMemorySize, SMEM_TOTAL);
    cudaFuncSetAttribute(mp_gemm_kernel<1>, cudaFuncAttributeMaxDynamicSharedMemorySize, SMEM_TOTAL);
    cudaFuncSetAttribute(mp_gemm_kernel<3>, cudaFuncAttributeMaxDynamicSharedMemorySize, SMEM_TOTAL);

    EdgeArgs ea;
    ea.off[0] = 0;
    for (int k = 0; k < 4; ++k) {
        ea.src[k] = srcs[k]; ea.dst[k] = dsts[k];
        ea.off[k + 1] = ea.off[k] + in_sizes[13 + 2 * k];
    }
    const int total_e = ea.off[4];

    const int NB = (NN + 127) / 128;
    const size_t NF = (size_t)NN * FH;
    const int NG = (int)(((size_t)NTOT * 32 + 255) / 256);

    // 0. fused prologue: W convert + x convert + degree count
    prologue_kernel<<<(NWELEM + NXELEM + total_e + 255) / 256, 256>>>(
        Ws1, Wn1, Ws2, Wn2, l1W, x, ea);

    // 1. scan (bases stay in g_part; consumers add them) + CSR fill
    scan1_kernel<<<SCAN_B, 1024>>>();
    scan2_kernel<<<1, 256>>>();
    fill_kernel<<<(total_e + 255) / 256, 256>>>(ea);

    // 2. layer-1 aggregation: gather mean of x -> agg bf16 (also zeroes degi/cur)
    gather_kernel<<<NG, 256>>>((const __nv_bfloat16*)xP, 0);

    // 3. layer-1 GEMM: h1 = relu(x@Ws1 + aggn@Wn1 + b1) -> bf16
    mp_gemm_kernel<0><<<dim3(NB, 4), 256, SMEM_TOTAL>>>(
        (const __nv_bfloat16*)xP, 0, (const __nv_bfloat16*)aggP, NF,
        0, 4, 1, b1, FH,
        (__nv_bfloat16*)h1P, NF, NN);

    // 4. layer-2 aggregation: gather mean of h1
    gather_kernel<<<NG, 256>>>((const __nv_bfloat16*)h1P, NF);

    // 5. layer-2 GEMM -> hstack bf16
    mp_gemm_kernel<1><<<dim3(NB, 4), 256, SMEM_TOTAL>>>(
        (const __nv_bfloat16*)h1P, NF, (const __nv_bfloat16*)aggP, NF,
        8, 12, 1, b2, FH,
        (__nv_bfloat16*)hsP, NF, NN);

    // 6. attention -> emb bf16
    attention_kernel<<<(NN * 32 + 255) / 256, 256>>>(attW, attB);

    // 7. P/Q GEMM: P = emb@W1a (y=0), Q = emb@W1b (y=1); no bias -> bf16
    mp_gemm_kernel<3><<<dim3(NB, 2), 256, SMEM_TOTAL>>>(
        (const __nv_bfloat16*)embP, 0, (const __nv_bfloat16*)embP, 0,
        16, 16, 1, l1b, 0,
        (__nv_bfloat16*)pqP, NF, NN);

    // 8. edge scorer: relu(P[s]+Q[d]+b) . w2 -> sigmoid
    edge_score_kernel<<<(int)(((size_t)esim * 32 + 255) / 256), 256>>>(
        ssim, dsim, l1b, l2W, l2b, (float*)d_out, esim);
}